// round 11
// baseline (speedup 1.0000x reference)
#include <cuda_runtime.h>
#include <cuda_bf16.h>

#define LSEQ 2048
#define NH 128
#define NSTATE 128

// Scratch for synthesized conv kernels Kl[h][l] (1 MB, static device global -> allowed)
__device__ float g_Kl[NH * LSEQ];

// ---------------------------------------------------------------------------
// Kernel 1: Kl[h,l] = dot(C[h,:], K[l,h,:]).  TWO rows per warp (rows 2g,2g+1
// are 1 KB contiguous in K_mats, same l, channels h0 and h0+1) -> 2 independent
// 512B loads in flight per warp = 64 KB/SM at full occupancy, past the HBM
// latency-hiding knee. K_mats layout (L,H,N) row-major. Streams 134 MB.
// ---------------------------------------------------------------------------
__global__ __launch_bounds__(256) void kl_kernel(const float* __restrict__ K,
                                                 const float* __restrict__ C) {
    int gw   = (blockIdx.x * 256 + threadIdx.x) >> 5;   // warp id; handles rows 2gw, 2gw+1
    int lane = threadIdx.x & 31;
    int r0   = gw * 2;                                  // even row
    int h0   = r0 & (NH - 1);                           // even channel; row1 -> h0+1
    int l    = r0 >> 7;                                 // same l for both rows

    const float4* krow = reinterpret_cast<const float4*>(K) + (size_t)r0 * 32;
    const float4* crow = reinterpret_cast<const float4*>(C) + (size_t)h0 * 32;
    float4 kv0 = krow[lane];        // row 2gw   (512B coalesced)
    float4 kv1 = krow[32 + lane];   // row 2gw+1 (next 512B, independent load)
    float4 cv0 = crow[lane];        // C[h0]   (L1-resident, 64 KB total)
    float4 cv1 = crow[32 + lane];   // C[h0+1]
    float p0 = kv0.x * cv0.x + kv0.y * cv0.y + kv0.z * cv0.z + kv0.w * cv0.w;
    float p1 = kv1.x * cv1.x + kv1.y * cv1.y + kv1.z * cv1.z + kv1.w * cv1.w;

#pragma unroll
    for (int off = 16; off > 0; off >>= 1) {
        p0 += __shfl_xor_sync(0xffffffffu, p0, off);
        p1 += __shfl_xor_sync(0xffffffffu, p1, off);
    }

    if (lane == 0) {
        g_Kl[h0 * LSEQ + l]       = p0;
        g_Kl[(h0 + 1) * LSEQ + l] = p1;
    }
}

// ---------------------------------------------------------------------------
// Kernel 2: depthwise 'same' conv + skip.
//   y[h,i] = sum_j Kl[h,j] * u[h, i+1023-j]  +  D[h]*u[h,i]
// One block per channel. u zero-padded in smem (offset UOFF=1025), k zero-padded
// to a multiple of 16 so every warp runs an exact multiple of 16 taps.
// Each thread computes 8 consecutive outputs via a 16-slot register sliding
// window; slot(addr) = (addr - i0) & 15, all indices compile-time constants.
// SMSP warp pairs {w, w+4} have complementary tap counts -> issue-balanced.
// ---------------------------------------------------------------------------
#define USZ  3328   // max padded-u index touched is 3327
#define KSZ  2064   // 2048 + 16 zero pad
#define UOFF 1025   // padded index = u index + 1025  (so bases are 0 mod 8/16)

__global__ __launch_bounds__(256) void conv_kernel(const float* __restrict__ u,
                                                   const float* __restrict__ D,
                                                   float* __restrict__ y) {
    __shared__ __align__(16) float s_u[USZ];
    __shared__ __align__(16) float s_k[KSZ];

    int h   = blockIdx.x;
    int tid = threadIdx.x;

    const float* urow = u + h * LSEQ;
    for (int p = tid; p < USZ; p += 256) {
        int q = p - UOFF;
        s_u[p] = (q >= 0 && q < LSEQ) ? urow[q] : 0.0f;
    }
    const float* krow = g_Kl + h * LSEQ;
    for (int p = tid; p < KSZ; p += 256)
        s_k[p] = (p < LSEQ) ? krow[p] : 0.0f;
    __syncthreads();

    int warp  = tid >> 5;
    int i0    = tid * 8;           // this thread's outputs: i0 .. i0+7
    int wbase = warp * 256;        // warp's output tile base
    // taps with any contribution for this warp's 256 outputs
    int jlo = (wbase > 1024) ? (wbase - 1024) : 0;        // multiple of 16
    int jhi = wbase + 1278; if (jhi > 2047) jhi = 2047;
    int cnt = (jhi - jlo + 1 + 15) & ~15;                 // padded taps are zeros

    float acc[8];
#pragma unroll
    for (int r = 0; r < 8; ++r) acc[r] = 0.0f;

    // sliding window: slot k holds s_u[a] with (a - i0) mod 16 == k
    float w[16];
    int b0 = i0 + 2048 - jlo;      // padded-u base at j = jlo  (b0 % 8 == 0)
    {
        float4 a = *reinterpret_cast<const float4*>(&s_u[b0]);
        float4 c = *reinterpret_cast<const float4*>(&s_u[b0 + 4]);
        w[0] = a.x; w[1] = a.y; w[2] = a.z; w[3] = a.w;
        w[4] = c.x; w[5] = c.y; w[6] = c.z; w[7] = c.w;
    }

    int j = jlo;
    int b = b0;
    for (int it = 0; it < cnt; it += 16) {
        // 16 taps, warp-uniform broadcast loads
        float4 ka = *reinterpret_cast<const float4*>(&s_k[j]);
        float4 kb = *reinterpret_cast<const float4*>(&s_k[j + 4]);
        float4 kc = *reinterpret_cast<const float4*>(&s_k[j + 8]);
        float4 kd = *reinterpret_cast<const float4*>(&s_k[j + 12]);
        float kk[16] = {ka.x, ka.y, ka.z, ka.w, kb.x, kb.y, kb.z, kb.w,
                        kc.x, kc.y, kc.z, kc.w, kd.x, kd.y, kd.z, kd.w};

        // refill slots 8..15 with s_u[b-8 .. b-1]
        {
            float4 a = *reinterpret_cast<const float4*>(&s_u[b - 8]);
            float4 c = *reinterpret_cast<const float4*>(&s_u[b - 4]);
            w[8]  = a.x; w[9]  = a.y; w[10] = a.z; w[11] = a.w;
            w[12] = c.x; w[13] = c.y; w[14] = c.z; w[15] = c.w;
        }
#pragma unroll
        for (int p = 0; p < 8; ++p) {
            float kv = kk[p];
#pragma unroll
            for (int r = 0; r < 8; ++r)
                acc[r] += kv * w[(r - p) & 15];
        }
        // refill slots 0..7 with s_u[b-16 .. b-9] (slots dead after p=7)
        {
            float4 a = *reinterpret_cast<const float4*>(&s_u[b - 16]);
            float4 c = *reinterpret_cast<const float4*>(&s_u[b - 12]);
            w[0] = a.x; w[1] = a.y; w[2] = a.z; w[3] = a.w;
            w[4] = c.x; w[5] = c.y; w[6] = c.z; w[7] = c.w;
        }
#pragma unroll
        for (int p = 8; p < 16; ++p) {
            float kv = kk[p];
#pragma unroll
            for (int r = 0; r < 8; ++r)
                acc[r] += kv * w[(r - p) & 15];
        }
        j += 16;
        b -= 16;
    }

    float d = D[h];
    float out[8];
#pragma unroll
    for (int r = 0; r < 8; ++r)
        out[r] = acc[r] + d * s_u[UOFF + i0 + r];

    float4* yrow = reinterpret_cast<float4*>(y + h * LSEQ + i0);
    float4 o0 = {out[0], out[1], out[2], out[3]};
    float4 o1 = {out[4], out[5], out[6], out[7]};
    yrow[0] = o0;
    yrow[1] = o1;
}

// ---------------------------------------------------------------------------
// kernel_launch: map inputs by element count (all four sizes are distinct).
//   u:262144  C:16384  D:128  K_mats:33554432   -> y:262144 (float32)
// ---------------------------------------------------------------------------
extern "C" void kernel_launch(void* const* d_in, const int* in_sizes, int n_in,
                              void* d_out, int out_size) {
    const float* u = nullptr;
    const float* C = nullptr;
    const float* D = nullptr;
    const float* K = nullptr;
    for (int i = 0; i < n_in; ++i) {
        switch (in_sizes[i]) {
            case NH * LSEQ:          u = (const float*)d_in[i]; break;   // 262144
            case NH * NSTATE:        C = (const float*)d_in[i]; break;   // 16384
            case NH:                 D = (const float*)d_in[i]; break;   // 128
            default:
                if (in_sizes[i] == LSEQ * NH * NSTATE)                   // 33554432
                    K = (const float*)d_in[i];
                break;
        }
    }

    // Phase 1: synthesize Kl (two (l,h) rows per warp; 131072 warps)
    kl_kernel<<<(LSEQ * NH) / 16, 256>>>(K, C);
    // Phase 2: depthwise conv + skip (one block per channel)
    conv_kernel<<<NH, 256>>>(u, D, (float*)d_out);
}